// round 1
// baseline (speedup 1.0000x reference)
#include <cuda_runtime.h>
#include <math.h>
#include <float.h>

#define SEQ    2048
#define HID    2048
#define DHEAD  64
#define NQH    32
#define NKVH   4
#define QKV_COLS 2560   // (32 + 4 + 4) * 64

// Scratch (no cudaMalloc allowed)
__device__ float g_qkv[SEQ * QKV_COLS];           // [s, 2560]
__device__ float g_attn[SEQ * (NQH * DHEAD)];     // [s, 2048]

// ---------------------------------------------------------------------------
// GEMM: C[M,N] = A[M,K] @ B[N,K]^T   (A,B row-major; classic 128x128x16 tile)
// ---------------------------------------------------------------------------
template<int BM, int BN, int BK, int TM, int TN>
__global__ void __launch_bounds__(256, 2)
sgemm_nt(const float* __restrict__ A, const float* __restrict__ B,
         float* __restrict__ C, int M, int N, int K) {
    __shared__ float As[BK][BM];
    __shared__ float Bs[BK][BN];

    const int tid  = threadIdx.x;
    const int row0 = blockIdx.y * BM;
    const int col0 = blockIdx.x * BN;
    const int ty   = tid / (BN / TN);   // 0..15
    const int tx   = tid % (BN / TN);   // 0..15

    float acc[TM][TN];
#pragma unroll
    for (int i = 0; i < TM; i++)
#pragma unroll
        for (int j = 0; j < TN; j++) acc[i][j] = 0.f;

    const int lrow = tid / 4;         // 0..63
    const int lcol = (tid % 4) * 4;   // 0,4,8,12

    for (int k0 = 0; k0 < K; k0 += BK) {
#pragma unroll
        for (int p = 0; p < 2; p++) {
            int r = lrow + p * 64;
            float4 va = *reinterpret_cast<const float4*>(
                &A[(size_t)(row0 + r) * K + k0 + lcol]);
            As[lcol + 0][r] = va.x; As[lcol + 1][r] = va.y;
            As[lcol + 2][r] = va.z; As[lcol + 3][r] = va.w;
            float4 vb = *reinterpret_cast<const float4*>(
                &B[(size_t)(col0 + r) * K + k0 + lcol]);
            Bs[lcol + 0][r] = vb.x; Bs[lcol + 1][r] = vb.y;
            Bs[lcol + 2][r] = vb.z; Bs[lcol + 3][r] = vb.w;
        }
        __syncthreads();
#pragma unroll
        for (int kk = 0; kk < BK; kk++) {
            const float4* a4 = reinterpret_cast<const float4*>(&As[kk][ty * TM]);
            const float4* b4 = reinterpret_cast<const float4*>(&Bs[kk][tx * TN]);
            float4 a0 = a4[0], a1 = a4[1];
            float4 b0 = b4[0], b1 = b4[1];
            float a[TM] = {a0.x, a0.y, a0.z, a0.w, a1.x, a1.y, a1.z, a1.w};
            float b[TN] = {b0.x, b0.y, b0.z, b0.w, b1.x, b1.y, b1.z, b1.w};
#pragma unroll
            for (int i = 0; i < TM; i++)
#pragma unroll
                for (int j = 0; j < TN; j++)
                    acc[i][j] = fmaf(a[i], b[j], acc[i][j]);
        }
        __syncthreads();
    }

#pragma unroll
    for (int i = 0; i < TM; i++) {
        int r = row0 + ty * TM + i;
#pragma unroll
        for (int j = 0; j < TN; j += 4) {
            float4 v = make_float4(acc[i][j], acc[i][j + 1],
                                   acc[i][j + 2], acc[i][j + 3]);
            *reinterpret_cast<float4*>(&C[(size_t)r * N + col0 + tx * TN + j]) = v;
        }
    }
}

// ---------------------------------------------------------------------------
// RoPE in-place on q heads (0..31) and k heads (32..35) of g_qkv
// ---------------------------------------------------------------------------
__global__ void rope_kernel() {
    int idx = blockIdx.x * blockDim.x + threadIdx.x;
    const int total = SEQ * 36 * 32;
    if (idx >= total) return;
    int pair = idx & 31;
    int head = (idx >> 5) % 36;
    int s    = idx / (36 * 32);

    // inv_freq = theta^(-pair/32)
    float inv_freq = powf(10000.0f, -(float)pair / 32.0f);
    float ang = (float)s * inv_freq;
    float sn, cs;
    sincosf(ang, &sn, &cs);

    float* base = g_qkv + (size_t)s * QKV_COLS + head * DHEAD;
    float x1 = base[pair];
    float x2 = base[pair + 32];
    base[pair]      = x1 * cs - x2 * sn;
    base[pair + 32] = x2 * cs + x1 * sn;
}

// ---------------------------------------------------------------------------
// Flash attention fp32, causal, GQA (8 q-heads per kv-head)
// One block per (q-head, 64-row q block). 256 thr, 4x4 per thread on 64x64.
// ---------------------------------------------------------------------------
#define FA_SMEM ((4 * 64 * 65 + 3 * 64) * 4)

__global__ void __launch_bounds__(256)
flash_attn() {
    extern __shared__ float sm[];
    float* Qs   = sm;                 // [64][65]  (pre-scaled by 1/8)
    float* Ks   = Qs + 64 * 65;       // [64][65]
    float* Vs   = Ks + 64 * 65;       // [64][65]
    float* Ss   = Vs + 64 * 65;       // [64][65]  S then P
    float* m_s  = Ss + 64 * 65;       // [64]
    float* l_s  = m_s + 64;           // [64]
    float* al_s = l_s + 64;           // [64]

    const int head = blockIdx.x;      // 0..31
    const int qb   = blockIdx.y;      // 0..31
    const int tid  = threadIdx.x;
    const int ty   = tid / 16, tx = tid % 16;
    const int r0   = ty * 4, c0 = tx * 4;
    const int kvh  = head / 8;

    const int qcol = head * DHEAD;
    const int kcol = (NQH + kvh) * DHEAD;
    const int vcol = (NQH + NKVH + kvh) * DHEAD;

    // Load Q tile (scaled): 1024 float4, 4 per thread
#pragma unroll
    for (int p = 0; p < 4; p++) {
        int f4  = tid + p * 256;
        int row = f4 / 16;
        int c4  = (f4 % 16) * 4;
        float4 v = *reinterpret_cast<const float4*>(
            &g_qkv[(size_t)(qb * 64 + row) * QKV_COLS + qcol + c4]);
        Qs[row * 65 + c4 + 0] = v.x * 0.125f;
        Qs[row * 65 + c4 + 1] = v.y * 0.125f;
        Qs[row * 65 + c4 + 2] = v.z * 0.125f;
        Qs[row * 65 + c4 + 3] = v.w * 0.125f;
    }
    if (tid < 64) { m_s[tid] = -1e30f; l_s[tid] = 0.f; }

    float o[4][4];
#pragma unroll
    for (int i = 0; i < 4; i++)
#pragma unroll
        for (int j = 0; j < 4; j++) o[i][j] = 0.f;

    for (int kb = 0; kb <= qb; kb++) {
        __syncthreads();  // protect Ks/Vs from previous iter readers
        // Load K, V tiles
#pragma unroll
        for (int p = 0; p < 4; p++) {
            int f4  = tid + p * 256;
            int row = f4 / 16;
            int c4  = (f4 % 16) * 4;
            size_t gro = (size_t)(kb * 64 + row) * QKV_COLS;
            float4 vk = *reinterpret_cast<const float4*>(&g_qkv[gro + kcol + c4]);
            Ks[row * 65 + c4 + 0] = vk.x; Ks[row * 65 + c4 + 1] = vk.y;
            Ks[row * 65 + c4 + 2] = vk.z; Ks[row * 65 + c4 + 3] = vk.w;
            float4 vv = *reinterpret_cast<const float4*>(&g_qkv[gro + vcol + c4]);
            Vs[row * 65 + c4 + 0] = vv.x; Vs[row * 65 + c4 + 1] = vv.y;
            Vs[row * 65 + c4 + 2] = vv.z; Vs[row * 65 + c4 + 3] = vv.w;
        }
        __syncthreads();

        // S = Q K^T (4x4 per thread)
        float s[4][4];
#pragma unroll
        for (int i = 0; i < 4; i++)
#pragma unroll
            for (int j = 0; j < 4; j++) s[i][j] = 0.f;
#pragma unroll 8
        for (int kk = 0; kk < 64; kk++) {
            float a[4], b[4];
#pragma unroll
            for (int i = 0; i < 4; i++) a[i] = Qs[(r0 + i) * 65 + kk];
#pragma unroll
            for (int j = 0; j < 4; j++) b[j] = Ks[(c0 + j) * 65 + kk];
#pragma unroll
            for (int i = 0; i < 4; i++)
#pragma unroll
                for (int j = 0; j < 4; j++)
                    s[i][j] = fmaf(a[i], b[j], s[i][j]);
        }

        // causal mask on diagonal block
        if (kb == qb) {
#pragma unroll
            for (int i = 0; i < 4; i++)
#pragma unroll
                for (int j = 0; j < 4; j++)
                    if (c0 + j > r0 + i) s[i][j] = -1e30f;
        }

#pragma unroll
        for (int i = 0; i < 4; i++)
#pragma unroll
            for (int j = 0; j < 4; j++)
                Ss[(r0 + i) * 65 + c0 + j] = s[i][j];
        __syncthreads();

        // per-row online softmax stats (64 threads, one row each)
        if (tid < 64) {
            int r = tid;
            float rmax = -1e30f;
#pragma unroll 8
            for (int c = 0; c < 64; c++) rmax = fmaxf(rmax, Ss[r * 65 + c]);
            float mold = m_s[r];
            float mnew = fmaxf(mold, rmax);
            float alpha = __expf(mold - mnew);
            float l = l_s[r] * alpha;
#pragma unroll 8
            for (int c = 0; c < 64; c++) {
                float p = __expf(Ss[r * 65 + c] - mnew);
                Ss[r * 65 + c] = p;
                l += p;
            }
            m_s[r] = mnew; l_s[r] = l; al_s[r] = alpha;
        }
        __syncthreads();

        // O = O*alpha + P @ V
        float al[4];
#pragma unroll
        for (int i = 0; i < 4; i++) al[i] = al_s[r0 + i];
#pragma unroll
        for (int i = 0; i < 4; i++)
#pragma unroll
            for (int j = 0; j < 4; j++) o[i][j] *= al[i];
#pragma unroll 8
        for (int kk = 0; kk < 64; kk++) {
            float p[4], v[4];
#pragma unroll
            for (int i = 0; i < 4; i++) p[i] = Ss[(r0 + i) * 65 + kk];
#pragma unroll
            for (int j = 0; j < 4; j++) v[j] = Vs[kk * 65 + c0 + j];
#pragma unroll
            for (int i = 0; i < 4; i++)
#pragma unroll
                for (int j = 0; j < 4; j++)
                    o[i][j] = fmaf(p[i], v[j], o[i][j]);
        }
    }
    __syncthreads();

    // write out: attn[s, head*64 + d]
#pragma unroll
    for (int i = 0; i < 4; i++) {
        float inv_l = 1.0f / l_s[r0 + i];
        int srow = qb * 64 + r0 + i;
#pragma unroll
        for (int j = 0; j < 4; j++)
            g_attn[(size_t)srow * (NQH * DHEAD) + head * DHEAD + c0 + j] =
                o[i][j] * inv_l;
    }
}

// ---------------------------------------------------------------------------
extern "C" void kernel_launch(void* const* d_in, const int* in_sizes, int n_in,
                              void* d_out, int out_size) {
    const float* hidden = (const float*)d_in[0];   // [1,2048,2048]
    const float* w_qkv  = (const float*)d_in[1];   // [2560,2048]
    const float* w_o    = (const float*)d_in[2];   // [2048,2048]
    float*       out    = (float*)d_out;           // [1,2048,2048]

    float *qkv_ptr = nullptr, *attn_ptr = nullptr;
    cudaGetSymbolAddress((void**)&qkv_ptr, g_qkv);
    cudaGetSymbolAddress((void**)&attn_ptr, g_attn);

    cudaFuncSetAttribute(flash_attn,
                         cudaFuncAttributeMaxDynamicSharedMemorySize, FA_SMEM);

    // 1) QKV projection: [2048,2560] = hidden @ w_qkv^T
    sgemm_nt<128, 128, 16, 8, 8><<<dim3(QKV_COLS / 128, SEQ / 128), 256>>>(
        hidden, w_qkv, qkv_ptr, SEQ, QKV_COLS, HID);

    // 2) RoPE on q + k heads
    {
        int total = SEQ * 36 * 32;
        rope_kernel<<<(total + 255) / 256, 256>>>();
    }

    // 3) Causal GQA flash attention
    flash_attn<<<dim3(NQH, SEQ / 64), 256, FA_SMEM>>>();

    // 4) Output projection: [2048,2048] = attn @ w_o^T
    sgemm_nt<128, 128, 16, 8, 8><<<dim3(HID / 128, SEQ / 128), 256>>>(
        attn_ptr, w_o, out, SEQ, HID, HID);
}

// round 2
// speedup vs baseline: 1.5809x; 1.5809x over previous
#include <cuda_runtime.h>
#include <cuda_bf16.h>
#include <math.h>
#include <float.h>
#include <stdint.h>

#define SEQ    2048
#define HID    2048
#define DHEAD  64
#define NQH    32
#define NKVH   4
#define QKV_COLS 2560   // (32 + 4 + 4) * 64

// ---------------- scratch (no cudaMalloc allowed) ----------------
__device__ float g_qkv [SEQ * QKV_COLS];          // fp32 QKV (attention input)
__device__ float g_attn[SEQ * (NQH * DHEAD)];     // fp32 attention output

__device__ __nv_bfloat16 g_hid_hi[SEQ * HID];
__device__ __nv_bfloat16 g_hid_lo[SEQ * HID];
__device__ __nv_bfloat16 g_wq_hi [QKV_COLS * HID];
__device__ __nv_bfloat16 g_wq_lo [QKV_COLS * HID];
__device__ __nv_bfloat16 g_wo_hi [HID * HID];
__device__ __nv_bfloat16 g_wo_lo [HID * HID];
__device__ __nv_bfloat16 g_at_hi [SEQ * HID];
__device__ __nv_bfloat16 g_at_lo [SEQ * HID];

// ---------------------------------------------------------------------------
// fp32 -> (bf16 hi, bf16 lo) split
// ---------------------------------------------------------------------------
__global__ void split_bf16(const float* __restrict__ in,
                           __nv_bfloat16* __restrict__ hi,
                           __nv_bfloat16* __restrict__ lo, int n) {
    int i = blockIdx.x * blockDim.x + threadIdx.x;
    if (i >= n) return;
    float x = in[i];
    __nv_bfloat16 h = __float2bfloat16(x);
    float r = x - __bfloat162float(h);
    hi[i] = h;
    lo[i] = __float2bfloat16(r);
}

// ---------------------------------------------------------------------------
// bf16x3 tensor-core GEMM: C[M,N] = A[M,K] @ B[N,K]^T  (fp32 accumulate)
// A,B given as (hi,lo) bf16 pairs. 128x128x32 CTA tile, 8 warps (2x4),
// warp tile 64x32, mma.sync.m16n8k16, cp.async double buffering.
// ---------------------------------------------------------------------------
#define BM 128
#define BN 128
#define BK 32
#define SROW 40                       // padded row stride (bf16 elems)
#define BUF_ELEMS (128 * SROW)        // 5120 bf16 per tile buffer
#define STAGE_ELEMS (4 * BUF_ELEMS)   // Ahi,Alo,Bhi,Blo
#define GEMM_SMEM (2 * STAGE_ELEMS * 2)  // bytes = 81920

__device__ __forceinline__ void cp16(uint32_t s, const void* g) {
    asm volatile("cp.async.cg.shared.global [%0], [%1], 16;\n" :: "r"(s), "l"(g));
}
__device__ __forceinline__ void cp_commit() {
    asm volatile("cp.async.commit_group;\n");
}
template<int N>
__device__ __forceinline__ void cp_wait() {
    asm volatile("cp.async.wait_group %0;\n" :: "n"(N));
}

__device__ __forceinline__ void mma16816(float* d, const uint32_t* a,
                                         const uint32_t* b) {
    asm volatile(
        "mma.sync.aligned.m16n8k16.row.col.f32.bf16.bf16.f32 "
        "{%0,%1,%2,%3}, {%4,%5,%6,%7}, {%8,%9}, {%0,%1,%2,%3};\n"
        : "+f"(d[0]), "+f"(d[1]), "+f"(d[2]), "+f"(d[3])
        : "r"(a[0]), "r"(a[1]), "r"(a[2]), "r"(a[3]), "r"(b[0]), "r"(b[1]));
}

__global__ void __launch_bounds__(256, 1)
gemm_bf16x3(const __nv_bfloat16* __restrict__ Ahi,
            const __nv_bfloat16* __restrict__ Alo,
            const __nv_bfloat16* __restrict__ Bhi,
            const __nv_bfloat16* __restrict__ Blo,
            float* __restrict__ C, int M, int N, int K) {
    extern __shared__ __nv_bfloat16 smem[];
    const int tid  = threadIdx.x;
    const int warp = tid >> 5;
    const int lane = tid & 31;
    const int wm   = warp >> 2;        // 0..1
    const int wn   = warp & 3;         // 0..3
    const int g    = lane >> 2;        // group id 0..7
    const int t    = lane & 3;         // thread-in-group 0..3
    const int row0 = blockIdx.y * BM;
    const int col0 = blockIdx.x * BN;

    uint32_t smem_u32;
    asm("{ .reg .u64 tmp; cvta.to.shared.u64 tmp, %1; cvt.u32.u64 %0, tmp; }"
        : "=r"(smem_u32) : "l"(smem));

    float acc[4][4][4];
#pragma unroll
    for (int i = 0; i < 4; i++)
#pragma unroll
        for (int j = 0; j < 4; j++)
#pragma unroll
            for (int k = 0; k < 4; k++) acc[i][j][k] = 0.f;

    const int NIT = K / BK;

    auto load_stage = [&](int stage, int k0) {
        uint32_t sb = smem_u32 + stage * (STAGE_ELEMS * 2);
#pragma unroll
        for (int c = tid; c < 512; c += 256) {
            int row = c >> 2;
            int cc  = c & 3;
            uint32_t so = sb + row * (SROW * 2) + cc * 16;
            size_t ga = (size_t)(row0 + row) * K + k0 + cc * 8;
            size_t gb = (size_t)(col0 + row) * K + k0 + cc * 8;
            cp16(so,                      Ahi + ga);
            cp16(so + 1 * BUF_ELEMS * 2,  Alo + ga);
            cp16(so + 2 * BUF_ELEMS * 2,  Bhi + gb);
            cp16(so + 3 * BUF_ELEMS * 2,  Blo + gb);
        }
    };

    load_stage(0, 0);
    cp_commit();

    for (int it = 0; it < NIT; it++) {
        if (it + 1 < NIT) {
            load_stage((it + 1) & 1, (it + 1) * BK);
            cp_commit();
            cp_wait<1>();
        } else {
            cp_wait<0>();
        }
        __syncthreads();

        const __nv_bfloat16* As = smem + (it & 1) * STAGE_ELEMS;
        const __nv_bfloat16* Al = As + BUF_ELEMS;
        const __nv_bfloat16* Bs = As + 2 * BUF_ELEMS;
        const __nv_bfloat16* Bl = As + 3 * BUF_ELEMS;

#pragma unroll
        for (int ks = 0; ks < 2; ks++) {
            uint32_t ahi[4][4], alo[4][4], bhi[4][2], blo[4][2];
#pragma unroll
            for (int mt = 0; mt < 4; mt++) {
                int rb = wm * 64 + mt * 16;
                const __nv_bfloat16* pa = As + (rb + g) * SROW + ks * 16 + 2 * t;
                const __nv_bfloat16* pl = Al + (rb + g) * SROW + ks * 16 + 2 * t;
                ahi[mt][0] = *(const uint32_t*)(pa);
                ahi[mt][1] = *(const uint32_t*)(pa + 8 * SROW);
                ahi[mt][2] = *(const uint32_t*)(pa + 8);
                ahi[mt][3] = *(const uint32_t*)(pa + 8 * SROW + 8);
                alo[mt][0] = *(const uint32_t*)(pl);
                alo[mt][1] = *(const uint32_t*)(pl + 8 * SROW);
                alo[mt][2] = *(const uint32_t*)(pl + 8);
                alo[mt][3] = *(const uint32_t*)(pl + 8 * SROW + 8);
            }
#pragma unroll
            for (int nt = 0; nt < 4; nt++) {
                int cb = wn * 32 + nt * 8;
                const __nv_bfloat16* pb = Bs + (cb + g) * SROW + ks * 16 + 2 * t;
                const __nv_bfloat16* pq = Bl + (cb + g) * SROW + ks * 16 + 2 * t;
                bhi[nt][0] = *(const uint32_t*)(pb);
                bhi[nt][1] = *(const uint32_t*)(pb + 8);
                blo[nt][0] = *(const uint32_t*)(pq);
                blo[nt][1] = *(const uint32_t*)(pq + 8);
            }
#pragma unroll
            for (int mt = 0; mt < 4; mt++)
#pragma unroll
                for (int nt = 0; nt < 4; nt++) {
                    mma16816(acc[mt][nt], ahi[mt], bhi[nt]);
                    mma16816(acc[mt][nt], ahi[mt], blo[nt]);
                    mma16816(acc[mt][nt], alo[mt], bhi[nt]);
                }
        }
        __syncthreads();
    }

    // epilogue
#pragma unroll
    for (int mt = 0; mt < 4; mt++) {
        int r = row0 + wm * 64 + mt * 16 + g;
#pragma unroll
        for (int nt = 0; nt < 4; nt++) {
            int c = col0 + wn * 32 + nt * 8 + 2 * t;
            float2 v0 = make_float2(acc[mt][nt][0], acc[mt][nt][1]);
            float2 v1 = make_float2(acc[mt][nt][2], acc[mt][nt][3]);
            *(float2*)&C[(size_t)r * N + c]       = v0;
            *(float2*)&C[(size_t)(r + 8) * N + c] = v1;
        }
    }
}

// ---------------------------------------------------------------------------
// RoPE in-place on q heads (0..31) and k heads (32..35) of g_qkv
// ---------------------------------------------------------------------------
__global__ void rope_kernel() {
    int idx = blockIdx.x * blockDim.x + threadIdx.x;
    const int total = SEQ * 36 * 32;
    if (idx >= total) return;
    int pair = idx & 31;
    int head = (idx >> 5) % 36;
    int s    = idx / (36 * 32);

    float inv_freq = __expf(-(float)pair * (9.210340371976184f / 32.0f));
    float ang = (float)s * inv_freq;
    float sn, cs;
    sincosf(ang, &sn, &cs);

    float* base = g_qkv + (size_t)s * QKV_COLS + head * DHEAD;
    float x1 = base[pair];
    float x2 = base[pair + 32];
    base[pair]      = x1 * cs - x2 * sn;
    base[pair + 32] = x2 * cs + x1 * sn;
}

// ---------------------------------------------------------------------------
// Flash attention fp32, causal, GQA. Register online-softmax + shfl reductions.
// One block per (q-head, 64-row q block). 256 thr, 4x4 per thread on 64x64.
// ---------------------------------------------------------------------------
#define FA_SMEM (4 * 64 * 65 * 4)

__global__ void __launch_bounds__(256)
flash_attn() {
    extern __shared__ float sm[];
    float* Qs = sm;                 // [64][65] (pre-scaled)
    float* Ks = Qs + 64 * 65;
    float* Vs = Ks + 64 * 65;
    float* Ss = Vs + 64 * 65;       // P tile

    const int head = blockIdx.x;
    const int qb   = blockIdx.y;
    const int tid  = threadIdx.x;
    const int ty   = tid / 16, tx = tid % 16;
    const int r0   = ty * 4, c0 = tx * 4;
    const int kvh  = head / 8;

    const int qcol = head * DHEAD;
    const int kcol = (NQH + kvh) * DHEAD;
    const int vcol = (NQH + NKVH + kvh) * DHEAD;

#pragma unroll
    for (int p = 0; p < 4; p++) {
        int f4  = tid + p * 256;
        int row = f4 / 16;
        int c4  = (f4 % 16) * 4;
        float4 v = *reinterpret_cast<const float4*>(
            &g_qkv[(size_t)(qb * 64 + row) * QKV_COLS + qcol + c4]);
        Qs[row * 65 + c4 + 0] = v.x * 0.125f;
        Qs[row * 65 + c4 + 1] = v.y * 0.125f;
        Qs[row * 65 + c4 + 2] = v.z * 0.125f;
        Qs[row * 65 + c4 + 3] = v.w * 0.125f;
    }

    float m_i[4], l_i[4];
#pragma unroll
    for (int i = 0; i < 4; i++) { m_i[i] = -1e30f; l_i[i] = 0.f; }

    float o[4][4];
#pragma unroll
    for (int i = 0; i < 4; i++)
#pragma unroll
        for (int j = 0; j < 4; j++) o[i][j] = 0.f;

    for (int kb = 0; kb <= qb; kb++) {
        __syncthreads();
#pragma unroll
        for (int p = 0; p < 4; p++) {
            int f4  = tid + p * 256;
            int row = f4 / 16;
            int c4  = (f4 % 16) * 4;
            size_t gro = (size_t)(kb * 64 + row) * QKV_COLS;
            float4 vk = *reinterpret_cast<const float4*>(&g_qkv[gro + kcol + c4]);
            Ks[row * 65 + c4 + 0] = vk.x; Ks[row * 65 + c4 + 1] = vk.y;
            Ks[row * 65 + c4 + 2] = vk.z; Ks[row * 65 + c4 + 3] = vk.w;
            float4 vv = *reinterpret_cast<const float4*>(&g_qkv[gro + vcol + c4]);
            Vs[row * 65 + c4 + 0] = vv.x; Vs[row * 65 + c4 + 1] = vv.y;
            Vs[row * 65 + c4 + 2] = vv.z; Vs[row * 65 + c4 + 3] = vv.w;
        }
        __syncthreads();

        // S = Q K^T
        float s[4][4];
#pragma unroll
        for (int i = 0; i < 4; i++)
#pragma unroll
            for (int j = 0; j < 4; j++) s[i][j] = 0.f;
#pragma unroll 8
        for (int kk = 0; kk < 64; kk++) {
            float a[4], b[4];
#pragma unroll
            for (int i = 0; i < 4; i++) a[i] = Qs[(r0 + i) * 65 + kk];
#pragma unroll
            for (int j = 0; j < 4; j++) b[j] = Ks[(c0 + j) * 65 + kk];
#pragma unroll
            for (int i = 0; i < 4; i++)
#pragma unroll
                for (int j = 0; j < 4; j++)
                    s[i][j] = fmaf(a[i], b[j], s[i][j]);
        }

        if (kb == qb) {
#pragma unroll
            for (int i = 0; i < 4; i++)
#pragma unroll
                for (int j = 0; j < 4; j++)
                    if (c0 + j > r0 + i) s[i][j] = -1e30f;
        }

        // register online softmax: reduce over the 16 tx-lanes (same 4 rows)
        float rmax[4];
#pragma unroll
        for (int i = 0; i < 4; i++) {
            float m = fmaxf(fmaxf(s[i][0], s[i][1]), fmaxf(s[i][2], s[i][3]));
#pragma unroll
            for (int off = 8; off > 0; off >>= 1)
                m = fmaxf(m, __shfl_xor_sync(0xffffffffu, m, off));
            rmax[i] = m;
        }

        float alpha[4], rsum[4];
#pragma unroll
        for (int i = 0; i < 4; i++) {
            float mnew = fmaxf(m_i[i], rmax[i]);
            alpha[i] = __expf(m_i[i] - mnew);
            m_i[i] = mnew;
            float ssum = 0.f;
#pragma unroll
            for (int j = 0; j < 4; j++) {
                float p = __expf(s[i][j] - mnew);
                Ss[(r0 + i) * 65 + c0 + j] = p;
                ssum += p;
            }
            rsum[i] = ssum;
        }
#pragma unroll
        for (int i = 0; i < 4; i++) {
            float v = rsum[i];
#pragma unroll
            for (int off = 8; off > 0; off >>= 1)
                v += __shfl_xor_sync(0xffffffffu, v, off);
            l_i[i] = l_i[i] * alpha[i] + v;
        }
#pragma unroll
        for (int i = 0; i < 4; i++)
#pragma unroll
            for (int j = 0; j < 4; j++) o[i][j] *= alpha[i];
        __syncthreads();

        // O += P @ V
#pragma unroll 8
        for (int kk = 0; kk < 64; kk++) {
            float p[4], v[4];
#pragma unroll
            for (int i = 0; i < 4; i++) p[i] = Ss[(r0 + i) * 65 + kk];
#pragma unroll
            for (int j = 0; j < 4; j++) v[j] = Vs[kk * 65 + c0 + j];
#pragma unroll
            for (int i = 0; i < 4; i++)
#pragma unroll
                for (int j = 0; j < 4; j++)
                    o[i][j] = fmaf(p[i], v[j], o[i][j]);
        }
    }

#pragma unroll
    for (int i = 0; i < 4; i++) {
        float inv_l = 1.0f / l_i[i];
        int srow = qb * 64 + r0 + i;
#pragma unroll
        for (int j = 0; j < 4; j++)
            g_attn[(size_t)srow * (NQH * DHEAD) + head * DHEAD + c0 + j] =
                o[i][j] * inv_l;
    }
}

// ---------------------------------------------------------------------------
extern "C" void kernel_launch(void* const* d_in, const int* in_sizes, int n_in,
                              void* d_out, int out_size) {
    const float* hidden = (const float*)d_in[0];   // [1,2048,2048]
    const float* w_qkv  = (const float*)d_in[1];   // [2560,2048]
    const float* w_o    = (const float*)d_in[2];   // [2048,2048]
    float*       out    = (float*)d_out;           // [1,2048,2048]

    float *qkv_ptr = nullptr, *attn_ptr = nullptr;
    cudaGetSymbolAddress((void**)&qkv_ptr, g_qkv);
    cudaGetSymbolAddress((void**)&attn_ptr, g_attn);
    __nv_bfloat16 *hid_hi, *hid_lo, *wq_hi, *wq_lo, *wo_hi, *wo_lo, *at_hi, *at_lo;
    cudaGetSymbolAddress((void**)&hid_hi, g_hid_hi);
    cudaGetSymbolAddress((void**)&hid_lo, g_hid_lo);
    cudaGetSymbolAddress((void**)&wq_hi,  g_wq_hi);
    cudaGetSymbolAddress((void**)&wq_lo,  g_wq_lo);
    cudaGetSymbolAddress((void**)&wo_hi,  g_wo_hi);
    cudaGetSymbolAddress((void**)&wo_lo,  g_wo_lo);
    cudaGetSymbolAddress((void**)&at_hi,  g_at_hi);
    cudaGetSymbolAddress((void**)&at_lo,  g_at_lo);

    cudaFuncSetAttribute(flash_attn,
                         cudaFuncAttributeMaxDynamicSharedMemorySize, FA_SMEM);
    cudaFuncSetAttribute(gemm_bf16x3,
                         cudaFuncAttributeMaxDynamicSharedMemorySize, GEMM_SMEM);

    // split inputs into bf16 hi/lo
    split_bf16<<<(SEQ * HID + 255) / 256, 256>>>(hidden, hid_hi, hid_lo, SEQ * HID);
    split_bf16<<<(QKV_COLS * HID + 255) / 256, 256>>>(w_qkv, wq_hi, wq_lo, QKV_COLS * HID);
    split_bf16<<<(HID * HID + 255) / 256, 256>>>(w_o, wo_hi, wo_lo, HID * HID);

    // 1) QKV projection
    gemm_bf16x3<<<dim3(QKV_COLS / BN, SEQ / BM), 256, GEMM_SMEM>>>(
        hid_hi, hid_lo, wq_hi, wq_lo, qkv_ptr, SEQ, QKV_COLS, HID);

    // 2) RoPE
    {
        int total = SEQ * 36 * 32;
        rope_kernel<<<(total + 255) / 256, 256>>>();
    }

    // 3) causal GQA flash attention
    flash_attn<<<dim3(NQH, SEQ / 64), 256, FA_SMEM>>>();

    // 4) output projection
    split_bf16<<<(SEQ * HID + 255) / 256, 256>>>(attn_ptr, at_hi, at_lo, SEQ * HID);
    gemm_bf16x3<<<dim3(HID / BN, SEQ / BM), 256, GEMM_SMEM>>>(
        at_hi, at_lo, wo_hi, wo_lo, out, SEQ, HID, HID);
}

// round 3
// speedup vs baseline: 2.6895x; 1.7012x over previous
#include <cuda_runtime.h>
#include <cuda_bf16.h>
#include <cuda_fp16.h>
#include <math.h>
#include <float.h>
#include <stdint.h>

#define SEQ    2048
#define HID    2048
#define DHEAD  64
#define NQH    32
#define NKVH   4
#define QKV_COLS 2560   // (32 + 4 + 4) * 64

// ---------------- scratch (no cudaMalloc allowed) ----------------
__device__ float g_qkv [SEQ * QKV_COLS];          // fp32 QKV (rope input)

__device__ __nv_bfloat16 g_hid_hi[SEQ * HID];
__device__ __nv_bfloat16 g_hid_lo[SEQ * HID];
__device__ __nv_bfloat16 g_wq_hi [QKV_COLS * HID];
__device__ __nv_bfloat16 g_wq_lo [QKV_COLS * HID];
__device__ __nv_bfloat16 g_wo_hi [HID * HID];
__device__ __nv_bfloat16 g_wo_lo [HID * HID];
__device__ __nv_bfloat16 g_at_hi [SEQ * HID];     // flash output (bf16 hi/lo)
__device__ __nv_bfloat16 g_at_lo [SEQ * HID];

// fp16 hi/lo attention operands, head-major [head][s][d]
__device__ __half g_q_hi[NQH  * SEQ * DHEAD];
__device__ __half g_q_lo[NQH  * SEQ * DHEAD];
__device__ __half g_k_hi[NKVH * SEQ * DHEAD];
__device__ __half g_k_lo[NKVH * SEQ * DHEAD];
__device__ __half g_v_hi[NKVH * SEQ * DHEAD];
__device__ __half g_v_lo[NKVH * SEQ * DHEAD];

// ---------------------------------------------------------------------------
// async copy + mma helpers
// ---------------------------------------------------------------------------
__device__ __forceinline__ void cp16(uint32_t s, const void* g) {
    asm volatile("cp.async.cg.shared.global [%0], [%1], 16;\n" :: "r"(s), "l"(g));
}
__device__ __forceinline__ void cp_commit() {
    asm volatile("cp.async.commit_group;\n");
}
template<int N>
__device__ __forceinline__ void cp_wait() {
    asm volatile("cp.async.wait_group %0;\n" :: "n"(N));
}

__device__ __forceinline__ void mma16816(float* d, const uint32_t* a,
                                         const uint32_t* b) {
    asm volatile(
        "mma.sync.aligned.m16n8k16.row.col.f32.bf16.bf16.f32 "
        "{%0,%1,%2,%3}, {%4,%5,%6,%7}, {%8,%9}, {%0,%1,%2,%3};\n"
        : "+f"(d[0]), "+f"(d[1]), "+f"(d[2]), "+f"(d[3])
        : "r"(a[0]), "r"(a[1]), "r"(a[2]), "r"(a[3]), "r"(b[0]), "r"(b[1]));
}
__device__ __forceinline__ void mma_f16(float* d, const uint32_t* a,
                                        const uint32_t* b) {
    asm volatile(
        "mma.sync.aligned.m16n8k16.row.col.f32.f16.f16.f32 "
        "{%0,%1,%2,%3}, {%4,%5,%6,%7}, {%8,%9}, {%0,%1,%2,%3};\n"
        : "+f"(d[0]), "+f"(d[1]), "+f"(d[2]), "+f"(d[3])
        : "r"(a[0]), "r"(a[1]), "r"(a[2]), "r"(a[3]), "r"(b[0]), "r"(b[1]));
}
__device__ __forceinline__ void ldsm_x4(uint32_t* r, uint32_t addr) {
    asm volatile("ldmatrix.sync.aligned.m8n8.x4.shared.b16 {%0,%1,%2,%3}, [%4];\n"
        : "=r"(r[0]), "=r"(r[1]), "=r"(r[2]), "=r"(r[3]) : "r"(addr));
}
__device__ __forceinline__ void ldsm_x4_t(uint32_t* r, uint32_t addr) {
    asm volatile("ldmatrix.sync.aligned.m8n8.x4.trans.shared.b16 {%0,%1,%2,%3}, [%4];\n"
        : "=r"(r[0]), "=r"(r[1]), "=r"(r[2]), "=r"(r[3]) : "r"(addr));
}
__device__ __forceinline__ uint32_t smem_u32_of(const void* p) {
    uint32_t a;
    asm("{ .reg .u64 t; cvta.to.shared.u64 t, %1; cvt.u32.u64 %0, t; }"
        : "=r"(a) : "l"(p));
    return a;
}

// ---------------------------------------------------------------------------
// fp32 -> (bf16 hi, bf16 lo) split
// ---------------------------------------------------------------------------
__global__ void split_bf16(const float* __restrict__ in,
                           __nv_bfloat16* __restrict__ hi,
                           __nv_bfloat16* __restrict__ lo, int n) {
    int i = blockIdx.x * blockDim.x + threadIdx.x;
    if (i >= n) return;
    float x = in[i];
    __nv_bfloat16 h = __float2bfloat16(x);
    float r = x - __bfloat162float(h);
    hi[i] = h;
    lo[i] = __float2bfloat16(r);
}

// ---------------------------------------------------------------------------
// bf16x3 tensor-core GEMM (3-stage cp.async pipeline)
// C[M,N] = A[M,K] @ B[N,K]^T, fp32 accumulate
// ---------------------------------------------------------------------------
#define BM 128
#define BN 128
#define BK 32
#define SROW 40
#define BUF_ELEMS (128 * SROW)
#define STAGE_ELEMS (4 * BUF_ELEMS)
#define GEMM_SMEM (3 * STAGE_ELEMS * 2)   // 122880 bytes

__global__ void __launch_bounds__(256, 1)
gemm_bf16x3(const __nv_bfloat16* __restrict__ Ahi,
            const __nv_bfloat16* __restrict__ Alo,
            const __nv_bfloat16* __restrict__ Bhi,
            const __nv_bfloat16* __restrict__ Blo,
            float* __restrict__ C, int M, int N, int K) {
    extern __shared__ __nv_bfloat16 smem[];
    const int tid  = threadIdx.x;
    const int warp = tid >> 5;
    const int lane = tid & 31;
    const int wm   = warp >> 2;
    const int wn   = warp & 3;
    const int g    = lane >> 2;
    const int t    = lane & 3;
    const int row0 = blockIdx.y * BM;
    const int col0 = blockIdx.x * BN;

    uint32_t smem_b = smem_u32_of(smem);

    float acc[4][4][4];
#pragma unroll
    for (int i = 0; i < 4; i++)
#pragma unroll
        for (int j = 0; j < 4; j++)
#pragma unroll
            for (int k = 0; k < 4; k++) acc[i][j][k] = 0.f;

    const int NIT = K / BK;

    auto load_stage = [&](int stage, int k0) {
        uint32_t sb = smem_b + stage * (STAGE_ELEMS * 2);
#pragma unroll
        for (int c = tid; c < 512; c += 256) {
            int row = c >> 2;
            int cc  = c & 3;
            uint32_t so = sb + row * (SROW * 2) + cc * 16;
            size_t ga = (size_t)(row0 + row) * K + k0 + cc * 8;
            size_t gb = (size_t)(col0 + row) * K + k0 + cc * 8;
            cp16(so,                      Ahi + ga);
            cp16(so + 1 * BUF_ELEMS * 2,  Alo + ga);
            cp16(so + 2 * BUF_ELEMS * 2,  Bhi + gb);
            cp16(so + 3 * BUF_ELEMS * 2,  Blo + gb);
        }
    };

    load_stage(0, 0);
    cp_commit();
    load_stage(1, BK);
    cp_commit();

    for (int it = 0; it < NIT; it++) {
        if (it + 2 < NIT) { cp_wait<1>(); } else { cp_wait<0>(); }
        __syncthreads();
        if (it + 2 < NIT) {
            load_stage((it + 2) % 3, (it + 2) * BK);
            cp_commit();
        }

        const __nv_bfloat16* As = smem + (it % 3) * STAGE_ELEMS;
        const __nv_bfloat16* Al = As + BUF_ELEMS;
        const __nv_bfloat16* Bs = As + 2 * BUF_ELEMS;
        const __nv_bfloat16* Bl = As + 3 * BUF_ELEMS;

#pragma unroll
        for (int ks = 0; ks < 2; ks++) {
            uint32_t ahi[4][4], alo[4][4], bhi[4][2], blo[4][2];
#pragma unroll
            for (int mt = 0; mt < 4; mt++) {
                int rb = wm * 64 + mt * 16;
                const __nv_bfloat16* pa = As + (rb + g) * SROW + ks * 16 + 2 * t;
                const __nv_bfloat16* pl = Al + (rb + g) * SROW + ks * 16 + 2 * t;
                ahi[mt][0] = *(const uint32_t*)(pa);
                ahi[mt][1] = *(const uint32_t*)(pa + 8 * SROW);
                ahi[mt][2] = *(const uint32_t*)(pa + 8);
                ahi[mt][3] = *(const uint32_t*)(pa + 8 * SROW + 8);
                alo[mt][0] = *(const uint32_t*)(pl);
                alo[mt][1] = *(const uint32_t*)(pl + 8 * SROW);
                alo[mt][2] = *(const uint32_t*)(pl + 8);
                alo[mt][3] = *(const uint32_t*)(pl + 8 * SROW + 8);
            }
#pragma unroll
            for (int nt = 0; nt < 4; nt++) {
                int cb = wn * 32 + nt * 8;
                const __nv_bfloat16* pb = Bs + (cb + g) * SROW + ks * 16 + 2 * t;
                const __nv_bfloat16* pq = Bl + (cb + g) * SROW + ks * 16 + 2 * t;
                bhi[nt][0] = *(const uint32_t*)(pb);
                bhi[nt][1] = *(const uint32_t*)(pb + 8);
                blo[nt][0] = *(const uint32_t*)(pq);
                blo[nt][1] = *(const uint32_t*)(pq + 8);
            }
#pragma unroll
            for (int mt = 0; mt < 4; mt++)
#pragma unroll
                for (int nt = 0; nt < 4; nt++) {
                    mma16816(acc[mt][nt], ahi[mt], bhi[nt]);
                    mma16816(acc[mt][nt], ahi[mt], blo[nt]);
                    mma16816(acc[mt][nt], alo[mt], bhi[nt]);
                }
        }
        __syncthreads();
    }

#pragma unroll
    for (int mt = 0; mt < 4; mt++) {
        int r = row0 + wm * 64 + mt * 16 + g;
#pragma unroll
        for (int nt = 0; nt < 4; nt++) {
            int c = col0 + wn * 32 + nt * 8 + 2 * t;
            float2 v0 = make_float2(acc[mt][nt][0], acc[mt][nt][1]);
            float2 v1 = make_float2(acc[mt][nt][2], acc[mt][nt][3]);
            *(float2*)&C[(size_t)r * N + c]       = v0;
            *(float2*)&C[(size_t)(r + 8) * N + c] = v1;
        }
    }
}

// ---------------------------------------------------------------------------
// RoPE + fp16 hi/lo split: g_qkv -> head-major q/k/v arrays
// (Q additionally scaled by 1/sqrt(d) = 0.125)
// ---------------------------------------------------------------------------
__global__ void rope_split() {
    int idx = blockIdx.x * blockDim.x + threadIdx.x;
    const int total = SEQ * 40 * 32;
    if (idx >= total) return;
    int pair = idx & 31;
    int head = (idx >> 5) % 40;
    int s    = idx / (40 * 32);

    const float* base = g_qkv + (size_t)s * QKV_COLS + head * DHEAD;
    float x1 = base[pair];
    float x2 = base[pair + 32];
    float y1, y2;
    if (head < 36) {
        float inv_freq = __expf(-(float)pair * (9.210340371976184f / 32.0f));
        float ang = (float)s * inv_freq;
        float sn, cs;
        sincosf(ang, &sn, &cs);
        y1 = x1 * cs - x2 * sn;
        y2 = x2 * cs + x1 * sn;
    } else {
        y1 = x1; y2 = x2;
    }

    __half *dh, *dl;
    size_t off;
    if (head < 32) {
        y1 *= 0.125f; y2 *= 0.125f;
        off = ((size_t)head * SEQ + s) * DHEAD;
        dh = g_q_hi; dl = g_q_lo;
    } else if (head < 36) {
        off = ((size_t)(head - 32) * SEQ + s) * DHEAD;
        dh = g_k_hi; dl = g_k_lo;
    } else {
        off = ((size_t)(head - 36) * SEQ + s) * DHEAD;
        dh = g_v_hi; dl = g_v_lo;
    }
    __half h1 = __float2half_rn(y1);
    __half h2 = __float2half_rn(y2);
    dh[off + pair]      = h1;
    dh[off + pair + 32] = h2;
    dl[off + pair]      = __float2half_rn(y1 - __half2float(h1));
    dl[off + pair + 32] = __float2half_rn(y2 - __half2float(h2));
}

// ---------------------------------------------------------------------------
// Tensor-core flash attention (fp16x3), causal, GQA.
// Block = (head, 64 q rows). 128 threads = 4 warps; warp owns 16 q rows.
// ---------------------------------------------------------------------------
#define FSTRIDE 72                       // halfs per smem row (144 B)
#define FTILE (64 * FSTRIDE)             // halfs per tile array
#define FA_SMEM (6 * FTILE * 2)          // 55296 bytes

__global__ void __launch_bounds__(128)
flash_attn_tc() {
    extern __shared__ __half fsm[];
    // arrays: 0:Qhi 1:Qlo 2:Khi 3:Klo 4:Vhi 5:Vlo
    uint32_t sbase = smem_u32_of(fsm);

    const int head = blockIdx.x;
    const int qb   = gridDim.y - 1 - blockIdx.y;   // heavy blocks first
    const int tid  = threadIdx.x;
    const int w    = tid >> 5;
    const int lane = tid & 31;
    const int kvh  = head >> 3;
    const int r8   = lane & 7;
    const int sub  = lane >> 3;

    // ---- load Q tile (hi+lo) ----
    {
        const __half* gqh = g_q_hi + ((size_t)head * SEQ + qb * 64) * DHEAD;
        const __half* gql = g_q_lo + ((size_t)head * SEQ + qb * 64) * DHEAD;
#pragma unroll
        for (int i = 0; i < 8; i++) {
            int c   = tid + i * 128;       // 1024 chunks
            int arr = c >> 9;              // 0=hi, 1=lo
            int rem = c & 511;
            int row = rem >> 3;
            int ch  = rem & 7;
            uint32_t dst = sbase + arr * (FTILE * 2) + row * 144 + ch * 16;
            const __half* src = (arr ? gql : gqh) + row * DHEAD + ch * 8;
            cp16(dst, src);
        }
        cp_commit(); cp_wait<0>();
        __syncthreads();
    }

    // ---- hoist Q fragments into registers ----
    uint32_t qh[4][4], ql[4][4];
#pragma unroll
    for (int kk = 0; kk < 4; kk++) {
        uint32_t addr = sbase
            + (w * 16 + r8 + ((sub & 1) << 3)) * 144
            + kk * 32 + ((sub & 2) << 3);
        ldsm_x4(qh[kk], addr);
        ldsm_x4(ql[kk], addr + FTILE * 2);
    }

    float of[8][4];
#pragma unroll
    for (int f = 0; f < 8; f++)
#pragma unroll
        for (int j = 0; j < 4; j++) of[f][j] = 0.f;
    float m0 = -1e30f, m1 = -1e30f, l0 = 0.f, l1 = 0.f;

    const uint32_t sK = sbase + 2 * (FTILE * 2);
    const uint32_t sV = sbase + 4 * (FTILE * 2);

    for (int kb = 0; kb <= qb; kb++) {
        __syncthreads();   // previous iter's readers done
        {
            const size_t go = ((size_t)kvh * SEQ + kb * 64) * DHEAD;
#pragma unroll
            for (int i = 0; i < 16; i++) {
                int c   = tid + i * 128;   // 2048 chunks
                int arr = c >> 9;          // 0:Khi 1:Klo 2:Vhi 3:Vlo
                int rem = c & 511;
                int row = rem >> 3;
                int ch  = rem & 7;
                uint32_t dst = sbase + (2 + arr) * (FTILE * 2) + row * 144 + ch * 16;
                const __half* src;
                if      (arr == 0) src = g_k_hi + go;
                else if (arr == 1) src = g_k_lo + go;
                else if (arr == 2) src = g_v_hi + go;
                else               src = g_v_lo + go;
                src += row * DHEAD + ch * 8;
                cp16(dst, src);
            }
            cp_commit(); cp_wait<0>();
            __syncthreads();
        }

        // ---- S = Q K^T (fp16x3) ----
        float sf[8][4];
#pragma unroll
        for (int f = 0; f < 8; f++)
#pragma unroll
            for (int j = 0; j < 4; j++) sf[f][j] = 0.f;

#pragma unroll
        for (int p = 0; p < 4; p++) {
            uint32_t bh[4][4], bl[4][4];
#pragma unroll
            for (int kk = 0; kk < 4; kk++) {
                uint32_t addr = sK
                    + (p * 16 + ((sub & 2) << 2) + r8) * 144
                    + kk * 32 + ((sub & 1) << 4);
                ldsm_x4(bh[kk], addr);
                ldsm_x4(bl[kk], addr + FTILE * 2);
            }
#pragma unroll
            for (int kk = 0; kk < 4; kk++) {
                mma_f16(sf[2 * p],     qh[kk], &bh[kk][0]);
                mma_f16(sf[2 * p],     qh[kk], &bl[kk][0]);
                mma_f16(sf[2 * p],     ql[kk], &bh[kk][0]);
                mma_f16(sf[2 * p + 1], qh[kk], &bh[kk][2]);
                mma_f16(sf[2 * p + 1], qh[kk], &bl[kk][2]);
                mma_f16(sf[2 * p + 1], ql[kk], &bh[kk][2]);
            }
        }

        // ---- causal mask (diagonal block) ----
        if (kb == qb) {
            int rt0 = w * 16 + (lane >> 2);
#pragma unroll
            for (int f = 0; f < 8; f++) {
                int ct = 8 * f + 2 * (lane & 3);
                if (ct > rt0)         sf[f][0] = -1e30f;
                if (ct + 1 > rt0)     sf[f][1] = -1e30f;
                if (ct > rt0 + 8)     sf[f][2] = -1e30f;
                if (ct + 1 > rt0 + 8) sf[f][3] = -1e30f;
            }
        }

        // ---- online softmax (warp-local rows) ----
        float c0 = -1e30f, c1 = -1e30f;
#pragma unroll
        for (int f = 0; f < 8; f++) {
            c0 = fmaxf(c0, fmaxf(sf[f][0], sf[f][1]));
            c1 = fmaxf(c1, fmaxf(sf[f][2], sf[f][3]));
        }
        c0 = fmaxf(c0, __shfl_xor_sync(0xffffffffu, c0, 1));
        c0 = fmaxf(c0, __shfl_xor_sync(0xffffffffu, c0, 2));
        c1 = fmaxf(c1, __shfl_xor_sync(0xffffffffu, c1, 1));
        c1 = fmaxf(c1, __shfl_xor_sync(0xffffffffu, c1, 2));

        float mn0 = fmaxf(m0, c0), mn1 = fmaxf(m1, c1);
        float a0 = __expf(m0 - mn0), a1 = __expf(m1 - mn1);
        m0 = mn0; m1 = mn1;

        float s0 = 0.f, s1 = 0.f;
#pragma unroll
        for (int f = 0; f < 8; f++) {
            sf[f][0] = __expf(sf[f][0] - mn0);
            sf[f][1] = __expf(sf[f][1] - mn0);
            sf[f][2] = __expf(sf[f][2] - mn1);
            sf[f][3] = __expf(sf[f][3] - mn1);
            s0 += sf[f][0] + sf[f][1];
            s1 += sf[f][2] + sf[f][3];
        }
        s0 += __shfl_xor_sync(0xffffffffu, s0, 1);
        s0 += __shfl_xor_sync(0xffffffffu, s0, 2);
        s1 += __shfl_xor_sync(0xffffffffu, s1, 1);
        s1 += __shfl_xor_sync(0xffffffffu, s1, 2);
        l0 = l0 * a0 + s0;
        l1 = l1 * a1 + s1;

#pragma unroll
        for (int f = 0; f < 8; f++) {
            of[f][0] *= a0; of[f][1] *= a0;
            of[f][2] *= a1; of[f][3] *= a1;
        }

        // ---- P -> fp16 hi/lo A fragments ----
        uint32_t ph[4][4], pl[4][4];
#pragma unroll
        for (int kk = 0; kk < 4; kk++) {
#pragma unroll
            for (int half4 = 0; half4 < 4; half4++) {
                int f = 2 * kk + (half4 >> 1);
                int j = (half4 & 1) * 2;
                float v0 = sf[f][j], v1 = sf[f][j + 1];
                __half h0 = __float2half_rn(v0);
                __half h1 = __float2half_rn(v1);
                __half2 hp = __halves2half2(h0, h1);
                __half2 lp = __halves2half2(
                    __float2half_rn(v0 - __half2float(h0)),
                    __float2half_rn(v1 - __half2float(h1)));
                // A frag order: a0=(r,klo) a1=(r+8,klo) a2=(r,khi) a3=(r+8,khi)
                int slot = (half4 >> 1) * 2 + (half4 & 1);  // f-major -> a index
                ph[kk][slot] = *(uint32_t*)&hp;
                pl[kk][slot] = *(uint32_t*)&lp;
            }
        }

        // ---- O += P V (fp16x3) ----
#pragma unroll
        for (int p = 0; p < 4; p++) {
            uint32_t vh[4][4], vl[4][4];
#pragma unroll
            for (int kk = 0; kk < 4; kk++) {
                uint32_t addr = sV
                    + (kk * 16 + ((sub & 1) << 3) + r8) * 144
                    + p * 32 + ((sub & 2) << 3);
                ldsm_x4_t(vh[kk], addr);
                ldsm_x4_t(vl[kk], addr + FTILE * 2);
            }
#pragma unroll
            for (int kk = 0; kk < 4; kk++) {
                mma_f16(of[2 * p],     ph[kk], &vh[kk][0]);
                mma_f16(of[2 * p],     ph[kk], &vl[kk][0]);
                mma_f16(of[2 * p],     pl[kk], &vh[kk][0]);
                mma_f16(of[2 * p + 1], ph[kk], &vh[kk][2]);
                mma_f16(of[2 * p + 1], ph[kk], &vl[kk][2]);
                mma_f16(of[2 * p + 1], pl[kk], &vh[kk][2]);
            }
        }
    }

    // ---- normalize + write bf16 hi/lo ----
    float inv0 = 1.0f / l0, inv1 = 1.0f / l1;
    int rq = qb * 64 + w * 16 + (lane >> 2);
    int cb = head * DHEAD + 2 * (lane & 3);
#pragma unroll
    for (int f = 0; f < 8; f++) {
        int col = cb + 8 * f;
        float v00 = of[f][0] * inv0, v01 = of[f][1] * inv0;
        float v10 = of[f][2] * inv1, v11 = of[f][3] * inv1;
        __nv_bfloat16 h00 = __float2bfloat16(v00);
        __nv_bfloat16 h01 = __float2bfloat16(v01);
        __nv_bfloat16 h10 = __float2bfloat16(v10);
        __nv_bfloat16 h11 = __float2bfloat16(v11);
        __nv_bfloat162 hp0 = {h00, h01};
        __nv_bfloat162 hp1 = {h10, h11};
        __nv_bfloat162 lp0 = {__float2bfloat16(v00 - __bfloat162float(h00)),
                              __float2bfloat16(v01 - __bfloat162float(h01))};
        __nv_bfloat162 lp1 = {__float2bfloat16(v10 - __bfloat162float(h10)),
                              __float2bfloat16(v11 - __bfloat162float(h11))};
        *(uint32_t*)&g_at_hi[(size_t)rq * HID + col]       = *(uint32_t*)&hp0;
        *(uint32_t*)&g_at_hi[(size_t)(rq + 8) * HID + col] = *(uint32_t*)&hp1;
        *(uint32_t*)&g_at_lo[(size_t)rq * HID + col]       = *(uint32_t*)&lp0;
        *(uint32_t*)&g_at_lo[(size_t)(rq + 8) * HID + col] = *(uint32_t*)&lp1;
    }
}

// ---------------------------------------------------------------------------
extern "C" void kernel_launch(void* const* d_in, const int* in_sizes, int n_in,
                              void* d_out, int out_size) {
    const float* hidden = (const float*)d_in[0];
    const float* w_qkv  = (const float*)d_in[1];
    const float* w_o    = (const float*)d_in[2];
    float*       out    = (float*)d_out;

    float* qkv_ptr = nullptr;
    cudaGetSymbolAddress((void**)&qkv_ptr, g_qkv);
    __nv_bfloat16 *hid_hi, *hid_lo, *wq_hi, *wq_lo, *wo_hi, *wo_lo, *at_hi, *at_lo;
    cudaGetSymbolAddress((void**)&hid_hi, g_hid_hi);
    cudaGetSymbolAddress((void**)&hid_lo, g_hid_lo);
    cudaGetSymbolAddress((void**)&wq_hi,  g_wq_hi);
    cudaGetSymbolAddress((void**)&wq_lo,  g_wq_lo);
    cudaGetSymbolAddress((void**)&wo_hi,  g_wo_hi);
    cudaGetSymbolAddress((void**)&wo_lo,  g_wo_lo);
    cudaGetSymbolAddress((void**)&at_hi,  g_at_hi);
    cudaGetSymbolAddress((void**)&at_lo,  g_at_lo);

    cudaFuncSetAttribute(gemm_bf16x3,
                         cudaFuncAttributeMaxDynamicSharedMemorySize, GEMM_SMEM);
    cudaFuncSetAttribute(flash_attn_tc,
                         cudaFuncAttributeMaxDynamicSharedMemorySize, FA_SMEM);

    // split fp32 inputs into bf16 hi/lo
    split_bf16<<<(SEQ * HID + 255) / 256, 256>>>(hidden, hid_hi, hid_lo, SEQ * HID);
    split_bf16<<<(QKV_COLS * HID + 255) / 256, 256>>>(w_qkv, wq_hi, wq_lo,
                                                      QKV_COLS * HID);
    split_bf16<<<(HID * HID + 255) / 256, 256>>>(w_o, wo_hi, wo_lo, HID * HID);

    // 1) QKV projection
    gemm_bf16x3<<<dim3(QKV_COLS / BN, SEQ / BM), 256, GEMM_SMEM>>>(
        hid_hi, hid_lo, wq_hi, wq_lo, qkv_ptr, SEQ, QKV_COLS, HID);

    // 2) RoPE + fp16 hi/lo split into head-major q/k/v
    {
        int total = SEQ * 40 * 32;
        rope_split<<<(total + 255) / 256, 256>>>();
    }

    // 3) tensor-core causal GQA flash attention
    flash_attn_tc<<<dim3(NQH, SEQ / 64), 128, FA_SMEM>>>();

    // 4) output projection
    gemm_bf16x3<<<dim3(HID / BN, SEQ / BM), 256, GEMM_SMEM>>>(
        at_hi, at_lo, wo_hi, wo_lo, out, SEQ, HID, HID);
}